// round 3
// baseline (speedup 1.0000x reference)
#include <cuda_runtime.h>
#include <math.h>

// Problem constants
#define NB    256   // batch
#define CIN   256   // input channels
#define HW    784   // 28*28 spatial
#define DD    64    // prototype channel dim
#define PP    200   // num prototypes
#define NCLS  10

constexpr int STILE   = 128;  // spatial positions per sub-tile
constexpr int KC      = 32;   // k-chunk for GEMM1
constexpr int THREADS = 512;

// Shared memory layout (float offsets)
constexpr int OFF_W1  = 0;                       // [64][256]
constexpr int OFF_W2  = OFF_W1 + DD * CIN;       // [64][64]
constexpr int OFF_P   = OFF_W2 + DD * DD;        // [200][64]
constexpr int OFF_P2  = OFF_P  + PP * DD;        // [200]
constexpr int OFF_B1  = OFF_P2 + PP;             // [64]
constexpr int OFF_B2  = OFF_B1 + DD;             // [64]
constexpr int OFF_XS  = OFF_B2 + DD;             // [KC][STILE]
constexpr int OFF_HS  = OFF_XS + KC * STILE;     // [64][STILE]
constexpr int OFF_FS  = OFF_HS + DD * STILE;     // [64][STILE]
constexpr int OFF_X2  = OFF_FS + DD * STILE;     // [STILE]
constexpr int OFF_MIN = OFF_X2 + STILE;          // [200] (int bits)
constexpr int SMEM_FLOATS = OFF_MIN + PP;
constexpr int SMEM_BYTES  = SMEM_FLOATS * 4;     // ~217.7 KB

__global__ __launch_bounds__(THREADS, 1)
void proto_fused_kernel(const float* __restrict__ x,
                        const float* __restrict__ W1,
                        const float* __restrict__ b1,
                        const float* __restrict__ W2,
                        const float* __restrict__ b2,
                        const float* __restrict__ proto,
                        const float* __restrict__ lastW,
                        const float* __restrict__ lastB,
                        float* __restrict__ out_logits,
                        float* __restrict__ out_mind)
{
    extern __shared__ float sm[];
    float* sW1 = sm + OFF_W1;
    float* sW2 = sm + OFF_W2;
    float* sP  = sm + OFF_P;
    float* sP2 = sm + OFF_P2;
    float* sB1 = sm + OFF_B1;
    float* sB2 = sm + OFF_B2;
    float* sXS = sm + OFF_XS;
    float* sHS = sm + OFF_HS;
    float* sFS = sm + OFF_FS;
    float* sX2 = sm + OFF_X2;
    int*   sMind = (int*)(sm + OFF_MIN);

    const int tid   = threadIdx.x;
    const int n     = blockIdx.x;
    const int lane  = tid & 31;
    const int grp   = tid >> 5;      // 0..15
    const int dbase = grp * 4;       // 4 output-channel columns per thread
    const int sbase = lane * 4;      // 4 spatial positions per thread

    // ---- Cooperative load of persistent weights into smem ----
    {
        const float4* g = (const float4*)W1;
        float4* s4 = (float4*)sW1;
        for (int i = tid; i < (DD * CIN) / 4; i += THREADS) s4[i] = g[i];
    }
    {
        const float4* g = (const float4*)W2;
        float4* s4 = (float4*)sW2;
        for (int i = tid; i < (DD * DD) / 4; i += THREADS) s4[i] = g[i];
    }
    {
        const float4* g = (const float4*)proto;
        float4* s4 = (float4*)sP;
        for (int i = tid; i < (PP * DD) / 4; i += THREADS) s4[i] = g[i];
    }
    if (tid < DD) { sB1[tid] = b1[tid]; sB2[tid] = b2[tid]; }
    if (tid < PP) sMind[tid] = 0x7F7FFFFF;   // FLT_MAX bits (all dists >= 0)
    __syncthreads();
    if (tid < PP) {   // ||p||^2 per prototype
        const float* pr = sP + tid * DD;
        float s = 0.f;
        #pragma unroll 8
        for (int d = 0; d < DD; d++) s += pr[d] * pr[d];
        sP2[tid] = s;
    }
    __syncthreads();

    const float* xg = x + (size_t)n * CIN * HW;

    // ---- 7 spatial sub-tiles of 128 positions ----
    for (int st = 0; st < 7; st++) {
        const int s0 = st * STILE;
        const int validCnt = HW - s0;   // >=128 except last tile (16)

        // ===== GEMM1: h[s][d] = relu(sum_c x[c][s] * W1[d][c] + b1[d]) =====
        float acc[4][4];
        #pragma unroll
        for (int i = 0; i < 4; i++)
            #pragma unroll
            for (int j = 0; j < 4; j++) acc[i][j] = 0.f;

        for (int kc = 0; kc < CIN / KC; kc++) {
            __syncthreads();   // protect sXS (also fences prior-iter GEMM3 readers)
            // stage x chunk [KC][STILE], coalesced rows of 128
            #pragma unroll
            for (int j = 0; j < (KC * STILE) / THREADS; j++) {
                int i  = j * THREADS + tid;
                int k  = i >> 7;         // /128
                int sl = i & 127;
                int gs = s0 + sl;
                sXS[i] = (gs < HW) ? xg[(kc * KC + k) * HW + gs] : 0.f;
            }
            __syncthreads();
            const float* wrow = sW1 + dbase * CIN + kc * KC;
            #pragma unroll 8
            for (int k = 0; k < KC; k++) {
                const float4 a = *(const float4*)(sXS + k * STILE + sbase);
                const float av[4] = {a.x, a.y, a.z, a.w};
                #pragma unroll
                for (int di = 0; di < 4; di++) {
                    const float w = wrow[di * CIN + k];
                    #pragma unroll
                    for (int si = 0; si < 4; si++)
                        acc[si][di] = fmaf(av[si], w, acc[si][di]);
                }
            }
        }
        // relu(+b1), store h transposed [d][s]; zero per-position ||f||^2
        #pragma unroll
        for (int di = 0; di < 4; di++) {
            const float b = sB1[dbase + di];
            float4 v;
            v.x = fmaxf(acc[0][di] + b, 0.f);
            v.y = fmaxf(acc[1][di] + b, 0.f);
            v.z = fmaxf(acc[2][di] + b, 0.f);
            v.w = fmaxf(acc[3][di] + b, 0.f);
            *(float4*)(sHS + (dbase + di) * STILE + sbase) = v;
        }
        if (tid < STILE) sX2[tid] = 0.f;
        __syncthreads();

        // ===== GEMM2: f[s][d2] = sigmoid(sum_d1 h[d1][s] * W2[d2][d1] + b2) =====
        float acc2[4][4];
        #pragma unroll
        for (int i = 0; i < 4; i++)
            #pragma unroll
            for (int j = 0; j < 4; j++) acc2[i][j] = 0.f;
        {
            const float* wrow = sW2 + dbase * DD;
            #pragma unroll 8
            for (int k = 0; k < DD; k++) {
                const float4 a = *(const float4*)(sHS + k * STILE + sbase);
                const float av[4] = {a.x, a.y, a.z, a.w};
                #pragma unroll
                for (int di = 0; di < 4; di++) {
                    const float w = wrow[di * DD + k];
                    #pragma unroll
                    for (int si = 0; si < 4; si++)
                        acc2[si][di] = fmaf(av[si], w, acc2[si][di]);
                }
            }
        }
        // sigmoid, accumulate ||f||^2 per position, store f transposed [d][s]
        float xpart[4] = {0.f, 0.f, 0.f, 0.f};
        #pragma unroll
        for (int di = 0; di < 4; di++) {
            const float b = sB2[dbase + di];
            float4 v;
            v.x = 1.f / (1.f + __expf(-(acc2[0][di] + b)));
            v.y = 1.f / (1.f + __expf(-(acc2[1][di] + b)));
            v.z = 1.f / (1.f + __expf(-(acc2[2][di] + b)));
            v.w = 1.f / (1.f + __expf(-(acc2[3][di] + b)));
            xpart[0] += v.x * v.x;
            xpart[1] += v.y * v.y;
            xpart[2] += v.z * v.z;
            xpart[3] += v.w * v.w;
            *(float4*)(sFS + (dbase + di) * STILE + sbase) = v;
        }
        #pragma unroll
        for (int si = 0; si < 4; si++) atomicAdd(&sX2[sbase + si], xpart[si]);
        __syncthreads();

        // ===== GEMM3: xp[s][p]; dist = relu(x2 - 2*xp + p2); running min =====
        for (int pc = 0; pc < 4; pc++) {
            const int pbase = pc * 64 + dbase;   // warp-uniform
            if (pbase >= PP) break;
            float acc3[4][4];
            #pragma unroll
            for (int i = 0; i < 4; i++)
                #pragma unroll
                for (int j = 0; j < 4; j++) acc3[i][j] = 0.f;
            const float* prow = sP + pbase * DD;
            #pragma unroll 8
            for (int k = 0; k < DD; k++) {
                const float4 a = *(const float4*)(sFS + k * STILE + sbase);
                const float av[4] = {a.x, a.y, a.z, a.w};
                #pragma unroll
                for (int pj = 0; pj < 4; pj++) {
                    const float w = prow[pj * DD + k];
                    #pragma unroll
                    for (int si = 0; si < 4; si++)
                        acc3[si][pj] = fmaf(av[si], w, acc3[si][pj]);
                }
            }
            float xv[4];
            #pragma unroll
            for (int si = 0; si < 4; si++) xv[si] = sX2[sbase + si];
            #pragma unroll
            for (int pj = 0; pj < 4; pj++) {
                const float pn2 = sP2[pbase + pj];
                float m = 3.402823466e+38f;
                #pragma unroll
                for (int si = 0; si < 4; si++) {
                    float d = xv[si] - 2.f * acc3[si][pj] + pn2;
                    d = fmaxf(d, 0.f);
                    if (sbase + si < validCnt) m = fminf(m, d);
                }
                #pragma unroll
                for (int o = 16; o > 0; o >>= 1)
                    m = fminf(m, __shfl_xor_sync(0xffffffffu, m, o));
                if (lane == 0)
                    atomicMin(&sMind[pbase + pj], __float_as_int(m));
            }
        }
        // no sync needed here: next iteration syncs before touching shared state
    }
    __syncthreads();

    // ---- Outputs ----
    if (tid < PP)
        out_mind[n * PP + tid] = __int_as_float(sMind[tid]);
    if (tid < NCLS * 32) {
        const int cls = tid >> 5;
        float ssum = 0.f;
        for (int p = lane; p < PP; p += 32)
            ssum += __int_as_float(sMind[p]) * lastW[cls * PP + p];
        #pragma unroll
        for (int o = 16; o > 0; o >>= 1)
            ssum += __shfl_xor_sync(0xffffffffu, ssum, o);
        if (lane == 0)
            out_logits[n * NCLS + cls] = lastB[cls] - ssum;   // act = -min_dist
    }
}

extern "C" void kernel_launch(void* const* d_in, const int* in_sizes, int n_in,
                              void* d_out, int out_size) {
    (void)in_sizes; (void)n_in; (void)out_size;
    const float* x      = (const float*)d_in[0];
    const float* W1     = (const float*)d_in[1];
    const float* b1     = (const float*)d_in[2];
    const float* W2     = (const float*)d_in[3];
    const float* b2     = (const float*)d_in[4];
    const float* proto  = (const float*)d_in[5];
    const float* lastW  = (const float*)d_in[6];
    const float* lastB  = (const float*)d_in[7];
    float* out        = (float*)d_out;
    float* out_logits = out;                 // (256,10)
    float* out_mind   = out + NB * NCLS;     // (256,200)

    cudaFuncSetAttribute(proto_fused_kernel,
                         cudaFuncAttributeMaxDynamicSharedMemorySize, SMEM_BYTES);
    proto_fused_kernel<<<NB, THREADS, SMEM_BYTES>>>(
        x, W1, b1, W2, b2, proto, lastW, lastB, out_logits, out_mind);
}